// round 7
// baseline (speedup 1.0000x reference)
#include <cuda_runtime.h>

#define CIN    64
#define PW     38            // padded width (32 + 2*3)
#define PROWS  22            // 16 output rows + 3 halo each side
#define PLANE  (PROWS*PW)    // 836
#define NPIX   1024          // 32*32

#define PLANES_BYTES (4*PLANE*16)                    // ktA,ktB,vtA,vtB = 53504
#define SMEM_BYTES   (PLANES_BYTES + 1536*4 + 224)   // + wt + rels = 59872

typedef unsigned long long ull;

__device__ __forceinline__ ull ffma2(ull a, ull b, ull c) {
    ull d;
    asm("fma.rn.f32x2 %0, %1, %2, %3;" : "=l"(d) : "l"(a), "l"(b), "l"(c));
    return d;
}
__device__ __forceinline__ ull mul2(ull a, ull b) {
    ull d;
    asm("mul.rn.f32x2 %0, %1, %2;" : "=l"(d) : "l"(a), "l"(b));
    return d;
}
__device__ __forceinline__ ull pk2(float a, float b) {
    ull r;
    asm("mov.b64 %0, {%1, %2};" : "=l"(r) : "f"(a), "f"(b));
    return r;
}
__device__ __forceinline__ float2 upk2(ull v) {
    float2 t;
    asm("mov.b64 {%0, %1}, %2;" : "=f"(t.x), "=f"(t.y) : "l"(v));
    return t;
}
__device__ __forceinline__ float ex2(float s) {
    float r;
    asm("ex2.approx.ftz.f32 %0, %1;" : "=f"(r) : "f"(s));
    return r;
}

// Phase 2 for R=2: 2 outputs per thread, 8 shared window rows.
template<bool ISH>
__device__ __forceinline__ void phase2_run(
    const ulonglong2* __restrict__ ktA, const ulonglong2* __restrict__ ktB,
    const ulonglong2* __restrict__ vtA, const ulonglong2* __restrict__ vtB,
    const ull (&Q)[2][4], const float (&bias)[2][7],
    float (&Z)[2], ull (&aa)[2][4], int lrow0, int w)
{
    #pragma unroll
    for (int pr = 0; pr < 8; pr++) {          // local plane rows lrow0..lrow0+7
        const int rowoff = (lrow0 + pr)*PW + w;
        ull seed[2];
        if (ISH) {
            if (pr < 7)  seed[0] = pk2(bias[0][pr], 0.f);
            if (pr >= 1) seed[1] = pk2(bias[1][pr-1], 0.f);
        }
        #pragma unroll
        for (int j = 0; j < 7; j++) {
            const int off = rowoff + j;
            ulonglong2 ka = ktA[off], kb = ktB[off];
            float e[2];
            #pragma unroll
            for (int o = 0; o < 2; o++) {
                const int i = pr - o;          // tap row for output o
                if (i >= 0 && i < 7) {
                    ull c0 = ISH ? seed[o] : pk2(bias[o][j], 0.f);
                    ull s2 = ffma2(Q[o][0], ka.x,
                             ffma2(Q[o][1], ka.y,
                             ffma2(Q[o][2], kb.x,
                             ffma2(Q[o][3], kb.y, c0))));
                    float2 sf = upk2(s2);
                    e[o] = ex2(sf.x + sf.y);   // max-free softmax, log2 domain
                    Z[o] += e[o];
                }
            }
            ulonglong2 va = vtA[off], vb = vtB[off];
            #pragma unroll
            for (int o = 0; o < 2; o++) {
                const int i = pr - o;
                if (i >= 0 && i < 7) {
                    ull e2 = pk2(e[o], e[o]);
                    aa[o][0] = ffma2(e2, va.x, aa[o][0]);
                    aa[o][1] = ffma2(e2, va.y, aa[o][1]);
                    aa[o][2] = ffma2(e2, vb.x, aa[o][2]);
                    aa[o][3] = ffma2(e2, vb.y, aa[o][3]);
                }
            }
        }
    }
}

// One CTA per (b, g, half). 256 threads, 3 CTAs/SM (<=85 regs, 58.5KB smem).
// Each warp owns 2 output rows; thread = one column of 2 outputs.
// Planes hold 22 padded rows: the 16 owned rows + 3-row halos.
// Warps 0-2 additionally project the 3 halo rows' k/v (16 ch each).
__global__ __launch_bounds__(256, 3)
void attn_conv_fused(const float* __restrict__ x,
                     const float* __restrict__ wq,
                     const float* __restrict__ wk,
                     const float* __restrict__ wv,
                     const float* __restrict__ relh,
                     const float* __restrict__ relw,
                     const float* __restrict__ cval,
                     float* __restrict__ out)
{
    extern __shared__ char smem[];
    ulonglong2* ktA = (ulonglong2*)smem;
    ulonglong2* ktB = ktA + PLANE;
    ulonglong2* vtA = ktB + PLANE;
    ulonglong2* vtB = vtA + PLANE;
    float* wt   = (float*)(smem + PLANES_BYTES);     // [64 ci][24]
    float* rels = wt + 1536;                         // [7][8]

    const int g    = blockIdx.x;        // 0..7
    const int by   = blockIdx.y;        // 0..63
    const int b    = by >> 1;
    const int half = by & 1;
    const int S    = half * 16;         // first owned output row
    const int tid  = threadIdx.x;
    const int wr   = tid >> 5;          // warp 0..7
    const int w    = tid & 31;          // column
    const int r0   = S + wr*2;          // first of 2 owned rows (global)
    const bool isH = (g < 4);
    const float cvg = cval[g];

    // ---- stage weights (transposed ci-major) ----
    for (int idx = tid; idx < 1536; idx += 256) {
        int ci = idx / 24, c = idx % 24;
        float v;
        if (c < 8)       v = wq[(g*8 + c)        * 64 + ci];
        else if (c < 16) v = wk[(g*8 + (c - 8))  * 64 + ci];
        else             v = wv[(g*8 + (c - 16)) * 64 + ci];
        wt[idx] = v;
    }
    if (tid < 56) {
        int i = tid >> 3, c = tid & 7;
        rels[tid] = isH ? relh[(g*8 + c)*7 + i]
                        : relw[((g - 4)*8 + c)*7 + i];
    }
    // zero planes (vertical + horizontal zero-padding semantics)
    {
        ulonglong2 z; z.x = 0ULL; z.y = 0ULL;
        for (int idx = tid; idx < 4*PLANE; idx += 256) ((ulonglong2*)smem)[idx] = z;
    }
    __syncthreads();

    const ulonglong2* relp = (const ulonglong2*)rels;  // [7][2]
    const ull l2e2 = pk2(1.4426950408889634f, 1.4426950408889634f);
    const float* xb = x + (size_t)b * CIN * NPIX;

    // ---- Phase 1a: project own 2 pixels (q,k,v = 24 ch), single ci pass ----
    ull Q[2][4];
    float bias[2][7];
    {
        ull acc[2][12];
        #pragma unroll
        for (int e = 0; e < 2; e++)
            #pragma unroll
            for (int p = 0; p < 12; p++) acc[e][p] = 0ULL;

        #pragma unroll 8
        for (int ci = 0; ci < 64; ci++) {
            float x0 = xb[ci*NPIX + r0*32 + w];
            float x1 = xb[ci*NPIX + (r0+1)*32 + w];
            ull xp0 = pk2(x0, x0);
            ull xp1 = pk2(x1, x1);
            const ulonglong2* wrow = (const ulonglong2*)(wt + ci*24);
            #pragma unroll
            for (int p = 0; p < 6; p++) {
                ulonglong2 wv2 = wrow[p];
                acc[0][2*p]   = ffma2(xp0, wv2.x, acc[0][2*p]);
                acc[0][2*p+1] = ffma2(xp0, wv2.y, acc[0][2*p+1]);
                acc[1][2*p]   = ffma2(xp1, wv2.x, acc[1][2*p]);
                acc[1][2*p+1] = ffma2(xp1, wv2.y, acc[1][2*p+1]);
            }
        }
        #pragma unroll
        for (int e = 0; e < 2; e++) {
            // scale q by log2e so phase 2 can use exp2 directly
            Q[e][0] = mul2(acc[e][0], l2e2); Q[e][1] = mul2(acc[e][1], l2e2);
            Q[e][2] = mul2(acc[e][2], l2e2); Q[e][3] = mul2(acc[e][3], l2e2);
            #pragma unroll
            for (int i = 0; i < 7; i++) {
                ulonglong2 r01 = relp[i*2], r23 = relp[i*2 + 1];
                ull d = ffma2(Q[e][0], r01.x,
                        ffma2(Q[e][1], r01.y,
                        ffma2(Q[e][2], r23.x,
                        ffma2(Q[e][3], r23.y, 0ULL))));
                float2 df = upk2(d);
                bias[e][i] = df.x + df.y;
            }
            // local plane row for global unpadded row r: (r + 3) - S
            const int pi = (wr*2 + e + 3)*PW + (w + 3);
            ulonglong2 tkv;
            tkv.x = acc[e][4];  tkv.y = acc[e][5];  ktA[pi] = tkv;
            tkv.x = acc[e][6];  tkv.y = acc[e][7];  ktB[pi] = tkv;
            tkv.x = acc[e][8];  tkv.y = acc[e][9];  vtA[pi] = tkv;
            tkv.x = acc[e][10]; tkv.y = acc[e][11]; vtB[pi] = tkv;
        }
    }

    // ---- Phase 1b: halo k/v rows (3 rows x 32 cols), warps 0-2 ----
    if (tid < 96) {
        const int hr = tid >> 5;                       // 0..2
        const int hw = tid & 31;
        const int hrow   = half ? (13 + hr) : (16 + hr);   // global unpadded
        const int hlocal = half ? hr        : (19 + hr);   // plane row
        ull hacc[8];
        #pragma unroll
        for (int p = 0; p < 8; p++) hacc[p] = 0ULL;

        #pragma unroll 8
        for (int ci = 0; ci < 64; ci++) {
            float xv = xb[ci*NPIX + hrow*32 + hw];
            ull xp = pk2(xv, xv);
            const ulonglong2* wrow = (const ulonglong2*)(wt + ci*24);
            #pragma unroll
            for (int p = 2; p < 6; p++) {              // k,v channels only
                ulonglong2 wv2 = wrow[p];
                hacc[2*(p-2)]   = ffma2(xp, wv2.x, hacc[2*(p-2)]);
                hacc[2*(p-2)+1] = ffma2(xp, wv2.y, hacc[2*(p-2)+1]);
            }
        }
        const int pi = hlocal*PW + (hw + 3);
        ulonglong2 tkv;
        tkv.x = hacc[0]; tkv.y = hacc[1]; ktA[pi] = tkv;
        tkv.x = hacc[2]; tkv.y = hacc[3]; ktB[pi] = tkv;
        tkv.x = hacc[4]; tkv.y = hacc[5]; vtA[pi] = tkv;
        tkv.x = hacc[6]; tkv.y = hacc[7]; vtB[pi] = tkv;
    }
    __syncthreads();

    // ---- Phase 2 ----
    float Z[2] = {0.f, 0.f};
    ull aa[2][4];
    #pragma unroll
    for (int o = 0; o < 2; o++)
        #pragma unroll
        for (int p = 0; p < 4; p++) aa[o][p] = 0ULL;

    if (isH) phase2_run<true >(ktA, ktB, vtA, vtB, Q, bias, Z, aa, wr*2, w);
    else     phase2_run<false>(ktA, ktB, vtA, vtB, Q, bias, Z, aa, wr*2, w);

    // ---- epilogue: adaptive ring mask + normalize + store ----
    float* outbase = out + ((size_t)b * 64 + g * 8) * NPIX;
    #pragma unroll
    for (int o = 0; o < 2; o++) {
        const int h   = r0 + o;
        const int pos = h*32 + w;
        int r  = min(h, 31 - h);
        int lo = (h <= 31 - h) ? r : r + 1;
        int hi = 31 - r;
        float omv  = fminf(fmaxf(((float)(r - 15) + cvg*16.0f)*(1.0f/3.0f) + 1.0f,
                                 0.0f), 1.0f);
        float mval = (w >= lo && w <= hi) ? omv : 1.0f;
        float sc   = __fdividef(mval, Z[o]);

        float2 o01 = upk2(aa[o][0]), o23 = upk2(aa[o][1]);
        float2 o45 = upk2(aa[o][2]), o67 = upk2(aa[o][3]);
        outbase[0*NPIX + pos] = o01.x * sc;
        outbase[1*NPIX + pos] = o01.y * sc;
        outbase[2*NPIX + pos] = o23.x * sc;
        outbase[3*NPIX + pos] = o23.y * sc;
        outbase[4*NPIX + pos] = o45.x * sc;
        outbase[5*NPIX + pos] = o45.y * sc;
        outbase[6*NPIX + pos] = o67.x * sc;
        outbase[7*NPIX + pos] = o67.y * sc;
    }
}

extern "C" void kernel_launch(void* const* d_in, const int* in_sizes, int n_in,
                              void* d_out, int out_size)
{
    const float* x    = (const float*)d_in[0];
    const float* wq   = (const float*)d_in[1];
    const float* wk   = (const float*)d_in[2];
    const float* wv   = (const float*)d_in[3];
    const float* relh = (const float*)d_in[4];
    const float* relw = (const float*)d_in[5];
    const float* cv   = (const float*)d_in[6];
    float* out = (float*)d_out;

    cudaFuncSetAttribute(attn_conv_fused,
                         cudaFuncAttributeMaxDynamicSharedMemorySize, SMEM_BYTES);
    attn_conv_fused<<<dim3(8, 64), 256, SMEM_BYTES>>>(x, wq, wk, wv, relh, relw, cv, out);
}

// round 8
// speedup vs baseline: 1.3089x; 1.3089x over previous
#include <cuda_runtime.h>

#define CIN   64
#define PW    38            // padded width (32 + 2*3)
#define NPIX  1024          // 32*32
#define NPAD  (PW*PW)       // 1444

#define PLANES_BYTES (4*NPAD*16)                     // ktA,ktB,vtA,vtB = 92416
#define SMEM_BYTES   (PLANES_BYTES + 1536*4 + 224)   // + wt + rels = 98784

typedef unsigned long long ull;

__device__ __forceinline__ ull ffma2(ull a, ull b, ull c) {
    ull d;
    asm("fma.rn.f32x2 %0, %1, %2, %3;" : "=l"(d) : "l"(a), "l"(b), "l"(c));
    return d;
}
__device__ __forceinline__ ull add2(ull a, ull b) {
    ull d;
    asm("add.rn.f32x2 %0, %1, %2;" : "=l"(d) : "l"(a), "l"(b));
    return d;
}
__device__ __forceinline__ ull pk2(float a, float b) {
    ull r;
    asm("mov.b64 %0, {%1, %2};" : "=l"(r) : "f"(a), "f"(b));
    return r;
}
__device__ __forceinline__ float2 upk2(ull v) {
    float2 t;
    asm("mov.b64 {%0, %1}, %2;" : "=f"(t.x), "=f"(t.y) : "l"(v));
    return t;
}
__device__ __forceinline__ float ex2(float s) {
    float r;
    asm("ex2.approx.ftz.f32 %0, %1;" : "=f"(r) : "f"(s));
    return r;
}

// Phase 2 specialized on group class (isH uniform per CTA).
// Score dot is tree-split into two 2-deep FFMA2 chains (half the latency of a
// serial 4-chain); bias rides in the c-seed of chain A.
template<bool ISH>
__device__ __forceinline__ void phase2_run(
    const ulonglong2* __restrict__ ktA, const ulonglong2* __restrict__ ktB,
    const ulonglong2* __restrict__ vtA, const ulonglong2* __restrict__ vtB,
    const ull (&Q)[4][4], const float (&bias)[4][7],
    float (&Z)[4], ull (&aa)[4][4], int h0, int w)
{
    #pragma unroll
    for (int pr = 0; pr < 10; pr++) {         // padded window rows h0..h0+9
        const int rowoff = (h0 + pr)*PW + w;
        ull seed[4];
        if (ISH) {
            #pragma unroll
            for (int o = 0; o < 4; o++) {
                const int i = pr - o;
                if (i >= 0 && i < 7) seed[o] = pk2(bias[o][i], 0.f);
            }
        }
        #pragma unroll
        for (int j = 0; j < 7; j++) {
            const int off = rowoff + j;
            ulonglong2 ka = ktA[off], kb = ktB[off];
            float e[4];
            #pragma unroll
            for (int o = 0; o < 4; o++) {
                const int i = pr - o;          // tap row for output o
                if (i >= 0 && i < 7) {
                    ull c0 = ISH ? seed[o] : pk2(bias[o][j], 0.f);
                    ull cA = ffma2(Q[o][0], ka.x, ffma2(Q[o][1], ka.y, c0));
                    ull cB = ffma2(Q[o][2], kb.x, ffma2(Q[o][3], kb.y, 0ULL));
                    float2 sf = upk2(add2(cA, cB));
                    e[o] = ex2(sf.x + sf.y);   // max-free softmax, log2 domain
                    Z[o] += e[o];
                }
            }
            ulonglong2 va = vtA[off], vb = vtB[off];
            #pragma unroll
            for (int o = 0; o < 4; o++) {
                const int i = pr - o;
                if (i >= 0 && i < 7) {
                    ull e2 = pk2(e[o], e[o]);
                    aa[o][0] = ffma2(e2, va.x, aa[o][0]);
                    aa[o][1] = ffma2(e2, va.y, aa[o][1]);
                    aa[o][2] = ffma2(e2, vb.x, aa[o][2]);
                    aa[o][3] = ffma2(e2, vb.y, aa[o][3]);
                }
            }
        }
    }
}

// One CTA per (batch b, group g). 256 threads, 2 CTAs/SM resident.
// Each thread owns a column of 4 output rows.
// Phase 1: project q/k/v (f32x2 FMA); q weights pre-scaled by log2e at staging
// so phase 2 uses exp2 directly. q -> regs, k/v -> smem planes.
// Phase 2: R=4 row-blocked 7x7 local attention + adaptive ring mask.
__global__ __launch_bounds__(256, 2)
void attn_conv_fused(const float* __restrict__ x,
                     const float* __restrict__ wq,
                     const float* __restrict__ wk,
                     const float* __restrict__ wv,
                     const float* __restrict__ relh,
                     const float* __restrict__ relw,
                     const float* __restrict__ cval,
                     float* __restrict__ out)
{
    extern __shared__ char smem[];
    ulonglong2* ktA = (ulonglong2*)smem;
    ulonglong2* ktB = ktA + NPAD;
    ulonglong2* vtA = ktB + NPAD;
    ulonglong2* vtB = vtA + NPAD;
    float* wt   = (float*)(smem + PLANES_BYTES);     // [64 ci][24]
    float* rels = wt + 1536;                         // [7][8]

    const int g   = blockIdx.x;        // 0..7
    const int b   = blockIdx.y;
    const int tid = threadIdx.x;
    const int wr  = tid >> 5;          // warp 0..7
    const int w   = tid & 31;          // column
    const int h0  = wr * 4;            // first of 4 owned rows
    const bool isH = (g < 4);
    const float cvg = cval[g];         // early load, used in epilogue

    // ---- stage weights (transposed ci-major); q rows pre-scaled by log2e ----
    const float L2E = 1.4426950408889634f;
    for (int idx = tid; idx < 1536; idx += 256) {
        int ci = idx / 24, c = idx % 24;
        float v;
        if (c < 8)       v = wq[(g*8 + c)        * 64 + ci] * L2E;
        else if (c < 16) v = wk[(g*8 + (c - 8))  * 64 + ci];
        else             v = wv[(g*8 + (c - 16)) * 64 + ci];
        wt[idx] = v;
    }
    if (tid < 56) {
        int i = tid >> 3, c = tid & 7;
        rels[tid] = isH ? relh[(g*8 + c)*7 + i]
                        : relw[((g - 4)*8 + c)*7 + i];
    }
    // zero padded k/v planes (borders act as zero padding)
    {
        ulonglong2 z; z.x = 0ULL; z.y = 0ULL;
        for (int idx = tid; idx < 4*NPAD; idx += 256) ((ulonglong2*)smem)[idx] = z;
    }
    __syncthreads();

    const ulonglong2* relp = (const ulonglong2*)rels;  // [7][2]

    // ---- Phase 1: projection for the 4 owned pixels (2 passes of 2 rows) ----
    ull   Q[4][4];       // q (pre-scaled by log2e via weights), 8 ch packed
    float bias[4][7];    // (q . rel), already in log2 domain
    const float* xb = x + (size_t)b * CIN * NPIX;

    #pragma unroll
    for (int pass = 0; pass < 2; pass++) {
        const int r0 = h0 + 2*pass;
        ull acc[2][12];
        #pragma unroll
        for (int e = 0; e < 2; e++)
            #pragma unroll
            for (int p = 0; p < 12; p++) acc[e][p] = 0ULL;

        #pragma unroll 8
        for (int ci = 0; ci < 64; ci++) {
            float x0 = xb[ci*NPIX + r0*32 + w];
            float x1 = xb[ci*NPIX + (r0+1)*32 + w];
            ull xp0 = pk2(x0, x0);
            ull xp1 = pk2(x1, x1);
            const ulonglong2* wrow = (const ulonglong2*)(wt + ci*24);
            #pragma unroll
            for (int p = 0; p < 6; p++) {
                ulonglong2 wv2 = wrow[p];
                acc[0][2*p]   = ffma2(xp0, wv2.x, acc[0][2*p]);
                acc[0][2*p+1] = ffma2(xp0, wv2.y, acc[0][2*p+1]);
                acc[1][2*p]   = ffma2(xp1, wv2.x, acc[1][2*p]);
                acc[1][2*p+1] = ffma2(xp1, wv2.y, acc[1][2*p+1]);
            }
        }
        #pragma unroll
        for (int e = 0; e < 2; e++) {
            const int o = 2*pass + e;
            Q[o][0] = acc[e][0]; Q[o][1] = acc[e][1];
            Q[o][2] = acc[e][2]; Q[o][3] = acc[e][3];
            #pragma unroll
            for (int i = 0; i < 7; i++) {
                ulonglong2 r01 = relp[i*2], r23 = relp[i*2 + 1];
                ull cA = ffma2(Q[o][0], r01.x, ffma2(Q[o][1], r01.y, 0ULL));
                ull cB = ffma2(Q[o][2], r23.x, ffma2(Q[o][3], r23.y, 0ULL));
                float2 df = upk2(add2(cA, cB));
                bias[o][i] = df.x + df.y;
            }
            const int pi = (h0 + o + 3)*PW + (w + 3);
            ulonglong2 tkv;
            tkv.x = acc[e][4];  tkv.y = acc[e][5];  ktA[pi] = tkv;
            tkv.x = acc[e][6];  tkv.y = acc[e][7];  ktB[pi] = tkv;
            tkv.x = acc[e][8];  tkv.y = acc[e][9];  vtA[pi] = tkv;
            tkv.x = acc[e][10]; tkv.y = acc[e][11]; vtB[pi] = tkv;
        }
    }
    __syncthreads();

    // ---- Phase 2 ----
    float Z[4] = {0.f, 0.f, 0.f, 0.f};
    ull aa[4][4];
    #pragma unroll
    for (int o = 0; o < 4; o++)
        #pragma unroll
        for (int p = 0; p < 4; p++) aa[o][p] = 0ULL;

    if (isH) phase2_run<true >(ktA, ktB, vtA, vtB, Q, bias, Z, aa, h0, w);
    else     phase2_run<false>(ktA, ktB, vtA, vtB, Q, bias, Z, aa, h0, w);

    // ---- epilogue: adaptive ring mask + normalize + store ----
    float* outbase = out + ((size_t)b * 64 + g * 8) * NPIX;
    #pragma unroll
    for (int o = 0; o < 4; o++) {
        const int h   = h0 + o;
        const int pos = h*32 + w;
        int r  = min(h, 31 - h);
        int lo = (h <= 31 - h) ? r : r + 1;
        int hi = 31 - r;
        float omv  = fminf(fmaxf(((float)(r - 15) + cvg*16.0f)*(1.0f/3.0f) + 1.0f,
                                 0.0f), 1.0f);
        float mval = (w >= lo && w <= hi) ? omv : 1.0f;
        float sc   = __fdividef(mval, Z[o]);

        float2 o01 = upk2(aa[o][0]), o23 = upk2(aa[o][1]);
        float2 o45 = upk2(aa[o][2]), o67 = upk2(aa[o][3]);
        outbase[0*NPIX + pos] = o01.x * sc;
        outbase[1*NPIX + pos] = o01.y * sc;
        outbase[2*NPIX + pos] = o23.x * sc;
        outbase[3*NPIX + pos] = o23.y * sc;
        outbase[4*NPIX + pos] = o45.x * sc;
        outbase[5*NPIX + pos] = o45.y * sc;
        outbase[6*NPIX + pos] = o67.x * sc;
        outbase[7*NPIX + pos] = o67.y * sc;
    }
}

extern "C" void kernel_launch(void* const* d_in, const int* in_sizes, int n_in,
                              void* d_out, int out_size)
{
    const float* x    = (const float*)d_in[0];
    const float* wq   = (const float*)d_in[1];
    const float* wk   = (const float*)d_in[2];
    const float* wv   = (const float*)d_in[3];
    const float* relh = (const float*)d_in[4];
    const float* relw = (const float*)d_in[5];
    const float* cv   = (const float*)d_in[6];
    float* out = (float*)d_out;

    cudaFuncSetAttribute(attn_conv_fused,
                         cudaFuncAttributeMaxDynamicSharedMemorySize, SMEM_BYTES);
    attn_conv_fused<<<dim3(8, 32), 256, SMEM_BYTES>>>(x, wq, wk, wv, relh, relw, cv, out);
}

// round 10
// speedup vs baseline: 1.3227x; 1.0106x over previous
#include <cuda_runtime.h>

#define CIN   64
#define PW    38            // padded width (32 + 2*3)
#define NPIX  1024          // 32*32
#define NPAD  (PW*PW)       // 1444

#define PLANES_BYTES (4*NPAD*16)                     // ktA,ktB,vtA,vtB = 92416
#define SMEM_BYTES   (PLANES_BYTES + 1536*4 + 224)   // + wt + rels = 98784

typedef unsigned long long ull;

__device__ __forceinline__ ull ffma2(ull a, ull b, ull c) {
    ull d;
    asm("fma.rn.f32x2 %0, %1, %2, %3;" : "=l"(d) : "l"(a), "l"(b), "l"(c));
    return d;
}
__device__ __forceinline__ ull add2(ull a, ull b) {
    ull d;
    asm("add.rn.f32x2 %0, %1, %2;" : "=l"(d) : "l"(a), "l"(b));
    return d;
}
__device__ __forceinline__ ull pk2(float a, float b) {
    ull r;
    asm("mov.b64 %0, {%1, %2};" : "=l"(r) : "f"(a), "f"(b));
    return r;
}
__device__ __forceinline__ float2 upk2(ull v) {
    float2 t;
    asm("mov.b64 {%0, %1}, %2;" : "=f"(t.x), "=f"(t.y) : "l"(v));
    return t;
}
__device__ __forceinline__ float ex2(float s) {
    float r;
    asm("ex2.approx.ftz.f32 %0, %1;" : "=f"(r) : "f"(s));
    return r;
}

// Compute one bias seed: (q . rel_idx) packed as (bias, 0).
__device__ __forceinline__ ull mk_seed(const ull (&Qo)[4],
                                       const ulonglong2* __restrict__ relp,
                                       int ridx)
{
    ulonglong2 r01 = relp[ridx*2], r23 = relp[ridx*2 + 1];
    ull cA = ffma2(Qo[0], r01.x, ffma2(Qo[1], r01.y, 0ULL));
    ull cB = ffma2(Qo[2], r23.x, ffma2(Qo[3], r23.y, 0ULL));
    float2 df = upk2(add2(cA, cB));
    return pk2(df.x + df.y, 0.f);
}

// One tap: score (tree-split, bias in chain-A seed) -> exp2 -> V accumulate.
__device__ __forceinline__ void do_tap(
    const ull (&Qo)[4], ull seed,
    const ulonglong2& ka, const ulonglong2& kb,
    const ulonglong2& va, const ulonglong2& vb,
    float& Zo, ull (&ao)[4])
{
    ull cA = ffma2(Qo[0], ka.x, ffma2(Qo[1], ka.y, seed));
    ull cB = ffma2(Qo[2], kb.x, ffma2(Qo[3], kb.y, 0ULL));
    float2 sf = upk2(add2(cA, cB));
    float e = ex2(sf.x + sf.y);        // max-free softmax, log2 domain
    Zo += e;
    ull e2 = pk2(e, e);
    ao[0] = ffma2(e2, va.x, ao[0]);
    ao[1] = ffma2(e2, va.y, ao[1]);
    ao[2] = ffma2(e2, vb.x, ao[2]);
    ao[3] = ffma2(e2, vb.y, ao[3]);
}

// Phase 2, bias seeds computed just-in-time (4 live at a time, no bias[4][7]).
// ISH: pr outer (bias depends on tap row i = pr-o) -> seeds per pr.
// ISW: j outer  (bias depends on tap col j)        -> seeds per j, pr inner.
template<bool ISH>
__device__ __forceinline__ void phase2_run(
    const ulonglong2* __restrict__ ktA, const ulonglong2* __restrict__ ktB,
    const ulonglong2* __restrict__ vtA, const ulonglong2* __restrict__ vtB,
    const ulonglong2* __restrict__ relp,
    const ull (&Q)[4][4], float (&Z)[4], ull (&aa)[4][4], int h0, int w)
{
    if (ISH) {
        #pragma unroll
        for (int pr = 0; pr < 10; pr++) {     // padded window rows h0..h0+9
            ull seed[4];
            #pragma unroll
            for (int o = 0; o < 4; o++) {
                const int i = pr - o;
                if (i >= 0 && i < 7) seed[o] = mk_seed(Q[o], relp, i);
            }
            const int rowoff = (h0 + pr)*PW + w;
            #pragma unroll
            for (int j = 0; j < 7; j++) {
                const int off = rowoff + j;
                ulonglong2 ka = ktA[off], kb = ktB[off];
                ulonglong2 va = vtA[off], vb = vtB[off];
                #pragma unroll
                for (int o = 0; o < 4; o++) {
                    const int i = pr - o;
                    if (i >= 0 && i < 7)
                        do_tap(Q[o], seed[o], ka, kb, va, vb, Z[o], aa[o]);
                }
            }
        }
    } else {
        #pragma unroll
        for (int j = 0; j < 7; j++) {         // window columns
            ull seed[4];
            #pragma unroll
            for (int o = 0; o < 4; o++) seed[o] = mk_seed(Q[o], relp, j);
            #pragma unroll
            for (int pr = 0; pr < 10; pr++) {
                const int off = (h0 + pr)*PW + w + j;
                ulonglong2 ka = ktA[off], kb = ktB[off];
                ulonglong2 va = vtA[off], vb = vtB[off];
                #pragma unroll
                for (int o = 0; o < 4; o++) {
                    const int i = pr - o;
                    if (i >= 0 && i < 7)
                        do_tap(Q[o], seed[o], ka, kb, va, vb, Z[o], aa[o]);
                }
            }
        }
    }
}

// One CTA per (batch b, group g). 256 threads, 2 CTAs/SM resident.
// Each thread owns a column of 4 output rows.
// Phase 1: project q/k/v (f32x2 FMA); q weights pre-scaled by log2e at staging.
// Phase 2: R=4 row-blocked 7x7 local attention + adaptive ring mask.
__global__ __launch_bounds__(256, 2)
void attn_conv_fused(const float* __restrict__ x,
                     const float* __restrict__ wq,
                     const float* __restrict__ wk,
                     const float* __restrict__ wv,
                     const float* __restrict__ relh,
                     const float* __restrict__ relw,
                     const float* __restrict__ cval,
                     float* __restrict__ out)
{
    extern __shared__ char smem[];
    ulonglong2* ktA = (ulonglong2*)smem;
    ulonglong2* ktB = ktA + NPAD;
    ulonglong2* vtA = ktB + NPAD;
    ulonglong2* vtB = vtA + NPAD;
    float* wt   = (float*)(smem + PLANES_BYTES);     // [64 ci][24]
    float* rels = wt + 1536;                         // [7][8]

    const int g   = blockIdx.x;        // 0..7
    const int b   = blockIdx.y;
    const int tid = threadIdx.x;
    const int wr  = tid >> 5;          // warp 0..7
    const int w   = tid & 31;          // column
    const int h0  = wr * 4;            // first of 4 owned rows
    const bool isH = (g < 4);
    const float cvg = cval[g];         // early load, used in epilogue

    // ---- stage weights (transposed ci-major); q rows pre-scaled by log2e ----
    const float L2E = 1.4426950408889634f;
    for (int idx = tid; idx < 1536; idx += 256) {
        int ci = idx / 24, c = idx % 24;
        float v;
        if (c < 8)       v = wq[(g*8 + c)        * 64 + ci] * L2E;
        else if (c < 16) v = wk[(g*8 + (c - 8))  * 64 + ci];
        else             v = wv[(g*8 + (c - 16)) * 64 + ci];
        wt[idx] = v;
    }
    if (tid < 56) {
        int i = tid >> 3, c = tid & 7;
        // rel scaled by log2e too (q is scaled; bias must match exp2 domain):
        // bias = (q*L2E) . rel  -> q.rel*L2E only if rel unscaled. q already
        // carries L2E, so rel must stay raw.  (q_scaled . rel == L2E*(q.rel)) ok.
        rels[tid] = isH ? relh[(g*8 + c)*7 + i]
                        : relw[((g - 4)*8 + c)*7 + i];
    }
    // ---- zero ONLY the halo border of the k/v planes (420 cells/plane) ----
    {
        ulonglong2 z; z.x = 0ULL; z.y = 0ULL;
        for (int idx = tid; idx < 420; idx += 256) {
            int row, col;
            if (idx < 114)      { row = idx / 38;              col = idx % 38; }
            else if (idx < 228) { int k2 = idx - 114; row = 35 + k2/38; col = k2%38; }
            else                { int k2 = idx - 228; row = 3 + k2/6;
                                  int c6 = k2 % 6;  col = (c6 < 3) ? c6 : 32 + c6; }
            int off = row*PW + col;
            ktA[off] = z; ktB[off] = z; vtA[off] = z; vtB[off] = z;
        }
    }
    __syncthreads();

    const ulonglong2* relp = (const ulonglong2*)rels;  // [7][2]

    // ---- Phase 1: projection for the 4 owned pixels (2 passes of 2 rows) ----
    ull Q[4][4];         // q (carries log2e via staged weights), 8 ch packed
    const float* xb = x + (size_t)b * CIN * NPIX;

    #pragma unroll
    for (int pass = 0; pass < 2; pass++) {
        const int r0 = h0 + 2*pass;
        ull acc[2][12];
        #pragma unroll
        for (int e = 0; e < 2; e++)
            #pragma unroll
            for (int p = 0; p < 12; p++) acc[e][p] = 0ULL;

        #pragma unroll 8
        for (int ci = 0; ci < 64; ci++) {
            float x0 = xb[ci*NPIX + r0*32 + w];
            float x1 = xb[ci*NPIX + (r0+1)*32 + w];
            ull xp0 = pk2(x0, x0);
            ull xp1 = pk2(x1, x1);
            const ulonglong2* wrow = (const ulonglong2*)(wt + ci*24);
            #pragma unroll
            for (int p = 0; p < 6; p++) {
                ulonglong2 wv2 = wrow[p];
                acc[0][2*p]   = ffma2(xp0, wv2.x, acc[0][2*p]);
                acc[0][2*p+1] = ffma2(xp0, wv2.y, acc[0][2*p+1]);
                acc[1][2*p]   = ffma2(xp1, wv2.x, acc[1][2*p]);
                acc[1][2*p+1] = ffma2(xp1, wv2.y, acc[1][2*p+1]);
            }
        }
        #pragma unroll
        for (int e = 0; e < 2; e++) {
            const int o = 2*pass + e;
            Q[o][0] = acc[e][0]; Q[o][1] = acc[e][1];
            Q[o][2] = acc[e][2]; Q[o][3] = acc[e][3];
            const int pi = (h0 + o + 3)*PW + (w + 3);
            ulonglong2 tkv;
            tkv.x = acc[e][4];  tkv.y = acc[e][5];  ktA[pi] = tkv;
            tkv.x = acc[e][6];  tkv.y = acc[e][7];  ktB[pi] = tkv;
            tkv.x = acc[e][8];  tkv.y = acc[e][9];  vtA[pi] = tkv;
            tkv.x = acc[e][10]; tkv.y = acc[e][11]; vtB[pi] = tkv;
        }
    }
    __syncthreads();

    // ---- Phase 2 ----
    float Z[4] = {0.f, 0.f, 0.f, 0.f};
    ull aa[4][4];
    #pragma unroll
    for (int o = 0; o < 4; o++)
        #pragma unroll
        for (int p = 0; p < 4; p++) aa[o][p] = 0ULL;

    if (isH) phase2_run<true >(ktA, ktB, vtA, vtB, relp, Q, Z, aa, h0, w);
    else     phase2_run<false>(ktA, ktB, vtA, vtB, relp, Q, Z, aa, h0, w);

    // ---- epilogue: adaptive ring mask + normalize + store ----
    float* outbase = out + ((size_t)b * 64 + g * 8) * NPIX;
    #pragma unroll
    for (int o = 0; o < 4; o++) {
        const int h   = h0 + o;
        const int pos = h*32 + w;
        int r  = min(h, 31 - h);
        int lo = (h <= 31 - h) ? r : r + 1;
        int hi = 31 - r;
        float omv  = fminf(fmaxf(((float)(r - 15) + cvg*16.0f)*(1.0f/3.0f) + 1.0f,
                                 0.0f), 1.0f);
        float mval = (w >= lo && w <= hi) ? omv : 1.0f;
        float sc   = __fdividef(mval, Z[o]);

        float2 o01 = upk2(aa[o][0]), o23 = upk2(aa[o][1]);
        float2 o45 = upk2(aa[o][2]), o67 = upk2(aa[o][3]);
        outbase[0*NPIX + pos] = o01.x * sc;
        outbase[1*NPIX + pos] = o01.y * sc;
        outbase[2*NPIX + pos] = o23.x * sc;
        outbase[3*NPIX + pos] = o23.y * sc;
        outbase[4*NPIX + pos] = o45.x * sc;
        outbase[5*NPIX + pos] = o45.y * sc;
        outbase[6*NPIX + pos] = o67.x * sc;
        outbase[7*NPIX + pos] = o67.y * sc;
    }
}

extern "C" void kernel_launch(void* const* d_in, const int* in_sizes, int n_in,
                              void* d_out, int out_size)
{
    const float* x    = (const float*)d_in[0];
    const float* wq   = (const float*)d_in[1];
    const float* wk   = (const float*)d_in[2];
    const float* wv   = (const float*)d_in[3];
    const float* relh = (const float*)d_in[4];
    const float* relw = (const float*)d_in[5];
    const float* cv   = (const float*)d_in[6];
    float* out = (float*)d_out;

    cudaFuncSetAttribute(attn_conv_fused,
                         cudaFuncAttributeMaxDynamicSharedMemorySize, SMEM_BYTES);
    attn_conv_fused<<<dim3(8, 32), 256, SMEM_BYTES>>>(x, wq, wk, wv, relh, relw, cv, out);
}